// round 1
// baseline (speedup 1.0000x reference)
#include <cuda_runtime.h>
#include <math.h>

#define ALPHA 0.2f
#define BN_SCALE 0.99950037f   // 1/sqrt(1 + 1e-3)

// ---------------- scratch (device globals; no allocation) ----------------
__device__ float g_a1[4 * 256 * 256 * 32];   // after stage 1
__device__ float g_a2[4 * 128 * 128 * 32];   // after stage 2
__device__ float g_a3[4 * 64 * 64 * 32];     // after stage 3
__device__ float g_f0[4 * 64 * 64 * 32];     // after fw0
__device__ float g_f1[4 * 64 * 64 * 32];     // after fw1
__device__ float g_disp[4 * 64 * 64 * 2];    // coarse displacement

// ---------------- stage 1: conv3x3 (Cin=2) + BN + LReLU + avgpool2 --------
__global__ __launch_bounds__(256) void k_conv0(const float* __restrict__ fixed,
                                               const float* __restrict__ moving,
                                               const float* __restrict__ w0) {
    __shared__ float sw[576];                 // (3,3,2,32)
    int t = threadIdx.x;
    for (int i = t; i < 576; i += 256) sw[i] = w0[i];
    __syncthreads();

    int idx = blockIdx.x * 256 + t;           // 4*256*256 = 262144
    int b = idx >> 16;
    int rem = idx & 65535;
    int y = rem >> 8, x = rem & 255;

    float pool[32];
#pragma unroll
    for (int i = 0; i < 32; i++) pool[i] = 0.f;

    for (int p = 0; p < 4; p++) {
        int cy = 2 * y + (p >> 1), cx = 2 * x + (p & 1);
        float acc[32];
#pragma unroll
        for (int i = 0; i < 32; i++) acc[i] = 0.f;
        for (int ky = 0; ky < 3; ky++) {
            int iy = cy + ky - 1;
            if ((unsigned)iy >= 512u) continue;
            for (int kx = 0; kx < 3; kx++) {
                int ix = cx + kx - 1;
                if ((unsigned)ix >= 512u) continue;
                int off = (b << 18) + (iy << 9) + ix;
                float v0 = fixed[off];
                float v1 = moving[off];
                const float* wp = sw + ((ky * 3 + kx) * 2) * 32;
#pragma unroll
                for (int o4 = 0; o4 < 8; o4++) {
                    float4 wa = reinterpret_cast<const float4*>(wp)[o4];
                    float4 wb = reinterpret_cast<const float4*>(wp + 32)[o4];
                    acc[o4 * 4 + 0] += v0 * wa.x + v1 * wb.x;
                    acc[o4 * 4 + 1] += v0 * wa.y + v1 * wb.y;
                    acc[o4 * 4 + 2] += v0 * wa.z + v1 * wb.z;
                    acc[o4 * 4 + 3] += v0 * wa.w + v1 * wb.w;
                }
            }
        }
#pragma unroll
        for (int i = 0; i < 32; i++) {
            float tv = acc[i] * BN_SCALE;
            pool[i] += (tv > 0.f ? tv : ALPHA * tv);
        }
    }
    float* op = g_a1 + (size_t)idx * 32;
#pragma unroll
    for (int i = 0; i < 32; i++) op[i] = pool[i] * 0.25f;
}

// ---------------- 32->32 conv3x3 accumulation core ------------------------
template <int HIN>
__device__ __forceinline__ void conv32_accum(const float* __restrict__ in,
                                             const float* sw, int b, int cy,
                                             int cx, float acc[32]) {
    for (int ky = 0; ky < 3; ky++) {
        int iy = cy + ky - 1;
        if ((unsigned)iy >= (unsigned)HIN) continue;
        for (int kx = 0; kx < 3; kx++) {
            int ix = cx + kx - 1;
            if ((unsigned)ix >= (unsigned)HIN) continue;
            const float4* ip = reinterpret_cast<const float4*>(
                in + ((size_t)(b * HIN + iy) * HIN + ix) * 32);
            const float4* wr =
                reinterpret_cast<const float4*>(sw + (ky * 3 + kx) * 1024);
#pragma unroll
            for (int ic4 = 0; ic4 < 8; ic4++) {
                float4 iv = ip[ic4];
#pragma unroll
                for (int s = 0; s < 4; s++) {
                    float v = (s == 0) ? iv.x : (s == 1) ? iv.y
                                       : (s == 2) ? iv.z : iv.w;
                    const float4* w4 = wr + (ic4 * 4 + s) * 8;
#pragma unroll
                    for (int o4 = 0; o4 < 8; o4++) {
                        float4 wv = w4[o4];
                        acc[o4 * 4 + 0] += v * wv.x;
                        acc[o4 * 4 + 1] += v * wv.y;
                        acc[o4 * 4 + 2] += v * wv.z;
                        acc[o4 * 4 + 3] += v * wv.w;
                    }
                }
            }
        }
    }
}

// ---------------- conv3x3 + BN + LReLU + avgpool2 (32->32) ----------------
template <int HIN>
__device__ __forceinline__ void conv_pool32_body(const float* __restrict__ in,
                                                 float* __restrict__ out,
                                                 const float* __restrict__ w) {
    __shared__ float sw[9216];                // (3,3,32,32)
    int t = threadIdx.x;
    for (int i = t; i < 9216; i += 256) sw[i] = w[i];
    __syncthreads();

    const int HOUT = HIN / 2;
    int idx = blockIdx.x * 256 + t;           // 4*HOUT*HOUT total
    int b = idx / (HOUT * HOUT);
    int rem = idx - b * (HOUT * HOUT);
    int y = rem / HOUT, x = rem - y * HOUT;

    float pool[32];
#pragma unroll
    for (int i = 0; i < 32; i++) pool[i] = 0.f;

    for (int p = 0; p < 4; p++) {
        float acc[32];
#pragma unroll
        for (int i = 0; i < 32; i++) acc[i] = 0.f;
        conv32_accum<HIN>(in, sw, b, 2 * y + (p >> 1), 2 * x + (p & 1), acc);
#pragma unroll
        for (int i = 0; i < 32; i++) {
            float tv = acc[i] * BN_SCALE;
            pool[i] += (tv > 0.f ? tv : ALPHA * tv);
        }
    }
    float* op = out + (size_t)idx * 32;
#pragma unroll
    for (int i = 0; i < 32; i++) op[i] = pool[i] * 0.25f;
}

__global__ __launch_bounds__(256) void k_stage2(const float* __restrict__ w) {
    conv_pool32_body<256>(g_a1, g_a2, w);
}
__global__ __launch_bounds__(256) void k_stage3(const float* __restrict__ w) {
    conv_pool32_body<128>(g_a2, g_a3, w);
}

// ---------------- conv3x3 + BN + LReLU (32->32, 64x64, no pool) -----------
__device__ __forceinline__ void conv64_body(const float* __restrict__ in,
                                            float* __restrict__ out,
                                            const float* __restrict__ w) {
    __shared__ float sw[9216];
    int t = threadIdx.x;
    for (int i = t; i < 9216; i += 256) sw[i] = w[i];
    __syncthreads();

    int idx = blockIdx.x * 256 + t;           // 4*64*64 = 16384
    int b = idx >> 12;
    int rem = idx & 4095;
    int y = rem >> 6, x = rem & 63;

    float acc[32];
#pragma unroll
    for (int i = 0; i < 32; i++) acc[i] = 0.f;
    conv32_accum<64>(in, sw, b, y, x, acc);

    float* op = out + (size_t)idx * 32;
#pragma unroll
    for (int i = 0; i < 32; i++) {
        float tv = acc[i] * BN_SCALE;
        op[i] = (tv > 0.f ? tv : ALPHA * tv);
    }
}

__global__ __launch_bounds__(256) void k_fconv0(const float* __restrict__ w) {
    conv64_body(g_a3, g_f0, w);
}
__global__ __launch_bounds__(256) void k_fconv1(const float* __restrict__ w) {
    conv64_body(g_f0, g_f1, w);
}

// ---------------- pointwise pw0 (LReLU, no BN) then pw1 -> disp -----------
__global__ __launch_bounds__(256) void k_pw(const float* __restrict__ pw0,
                                            const float* __restrict__ pw1) {
    __shared__ float s0[1024];                // (1,1,32,32)
    __shared__ float s1[64];                  // (1,1,32,2)
    int t = threadIdx.x;
    for (int i = t; i < 1024; i += 256) s0[i] = pw0[i];
    if (t < 64) s1[t] = pw1[t];
    __syncthreads();

    int idx = blockIdx.x * 256 + t;           // 4*64*64 = 16384
    const float4* ip = reinterpret_cast<const float4*>(g_f1 + (size_t)idx * 32);
    float xv[32];
#pragma unroll
    for (int i = 0; i < 8; i++) {
        float4 v = ip[i];
        xv[i * 4 + 0] = v.x; xv[i * 4 + 1] = v.y;
        xv[i * 4 + 2] = v.z; xv[i * 4 + 3] = v.w;
    }
    float d0 = 0.f, d1 = 0.f;
#pragma unroll
    for (int oc = 0; oc < 32; oc++) {
        float a = 0.f;
#pragma unroll
        for (int ic = 0; ic < 32; ic++) a += xv[ic] * s0[ic * 32 + oc];
        a = (a > 0.f ? a : ALPHA * a);
        d0 += a * s1[oc * 2 + 0];
        d1 += a * s1[oc * 2 + 1];
    }
    g_disp[idx * 2 + 0] = d0;
    g_disp[idx * 2 + 1] = d1;
}

// ---------------- B-spline upsample + bilinear warp + outputs -------------
__global__ __launch_bounds__(256) void k_warp(const float* __restrict__ moving,
                                              float* __restrict__ out) {
    int idx = blockIdx.x * 256 + threadIdx.x; // 4*512*512
    int b = idx >> 18;
    int rem = idx & 262143;
    int h = rem >> 9, w = rem & 511;

    float xv = fminf(w * 0.125f, 63.f);
    float yv = fminf(h * 0.125f, 63.f);
    int ii = (int)xv;
    int jj = (int)yv;
    float u = xv * 0.015625f;                 // /64
    float v = yv * 0.015625f;

    float u2 = u * u, u3 = u2 * u;
    float v2 = v * v, v3 = v2 * v;
    // bvec(t) @ COEFF, columns l=0..3
    float Bu[4] = { -u3 + 3.f * u2 - 3.f * u + 1.f,
                     3.f * u3 - 6.f * u2 + 4.f,
                    -3.f * u3 + 3.f * u2 + 3.f * u + 1.f,
                     u3 };
    float Bv[4] = { -v3 + 3.f * v2 - 3.f * v + 1.f,
                     3.f * v3 - 6.f * v2 + 4.f,
                    -3.f * v3 + 3.f * v2 + 3.f * v + 1.f,
                     v3 };

    const float2* dp = reinterpret_cast<const float2*>(g_disp);
    float i0 = 0.f, i1 = 0.f;
#pragma unroll
    for (int m = 0; m < 4; m++) {             // m offsets jj (rows), weighted by Bu
        int ry = jj + m - 1;
        if ((unsigned)ry >= 64u) continue;
        float s0 = 0.f, s1 = 0.f;
#pragma unroll
        for (int n = 0; n < 4; n++) {         // n offsets ii (cols), weighted by Bv
            int rx = ii + n - 1;
            if ((unsigned)rx >= 64u) continue;
            float2 d = dp[(b * 64 + ry) * 64 + rx];
            s0 += Bv[n] * d.x;
            s1 += Bv[n] * d.y;
        }
        i0 += Bu[m] * s0;
        i1 += Bu[m] * s1;
    }

    float wxf = i0 + (float)w;
    float wyf = i1 + (float)h;

    // bilinear (exactly mirroring reference with eps=1e-5)
    float fx = floorf(wxf);
    float x0 = fminf(fmaxf(fx, 0.f), 511.f);
    float x1 = fminf(fmaxf(fx + 1.f, 0.f), 511.f);
    float fy = floorf(wyf);
    float y0 = fminf(fmaxf(fy, 0.f), 511.f);
    float y1 = fminf(fmaxf(fy + 1.f, 0.f), 511.f);
    int x0i = (int)x0, x1i = (int)x1, y0i = (int)y0, y1i = (int)y1;

    const float* im = moving + ((size_t)b << 18);
    float Q1 = im[y0i * 512 + x0i];
    float Q2 = im[y1i * 512 + x0i];
    float Q3 = im[y0i * 512 + x1i];
    float Q4 = im[y1i * 512 + x1i];

    float invx = 1.f / (x1 - x0 + 1e-5f);
    float wxr = (x1 - wxf) * invx;
    float wxl = (wxf - x0) * invx;
    float R1 = wxr * Q1 + wxl * Q3;
    float R2 = wxr * Q2 + wxl * Q4;
    float invy = 1.f / (y1 - y0 + 1e-5f);
    float res = (y1 - wyf) * invy * R1 + (wyf - y0) * invy * R2;

    // outputs: warped [B,H,W,1] then warped_grid [B,2,H,W]
    out[(b << 18) + (h << 9) + w] = res;
    const int WOFF = 4 * 512 * 512;
    out[WOFF + ((b * 2 + 0) << 18) + (h << 9) + w] = wxf;
    out[WOFF + ((b * 2 + 1) << 18) + (h << 9) + w] = wyf;
}

// ---------------- launch ---------------------------------------------------
extern "C" void kernel_launch(void* const* d_in, const int* in_sizes, int n_in,
                              void* d_out, int out_size) {
    const float* fixed  = (const float*)d_in[0];
    const float* moving = (const float*)d_in[1];
    const float* w0  = (const float*)d_in[2];
    const float* w1  = (const float*)d_in[3];
    const float* w2  = (const float*)d_in[4];
    const float* fw0 = (const float*)d_in[5];
    const float* fw1 = (const float*)d_in[6];
    const float* pw0 = (const float*)d_in[7];
    const float* pw1 = (const float*)d_in[8];
    float* out = (float*)d_out;

    k_conv0<<<262144 / 256, 256>>>(fixed, moving, w0);   // 512 -> 256
    k_stage2<<<65536 / 256, 256>>>(w1);                  // 256 -> 128
    k_stage3<<<16384 / 256, 256>>>(w2);                  // 128 -> 64
    k_fconv0<<<16384 / 256, 256>>>(fw0);                 // 64x64 conv
    k_fconv1<<<16384 / 256, 256>>>(fw1);                 // 64x64 conv
    k_pw<<<16384 / 256, 256>>>(pw0, pw1);                // pointwise -> disp
    k_warp<<<1048576 / 256, 256>>>(moving, out);         // upsample + warp
}

// round 8
// speedup vs baseline: 1.3080x; 1.3080x over previous
#include <cuda_runtime.h>
#include <math.h>

#define ALPHA 0.2f
#define BN_SCALE 0.99950037f   // 1/sqrt(1 + 1e-3)

typedef unsigned long long u64;

// ---------------- packed f32x2 helpers ------------------------------------
__device__ __forceinline__ u64 pack2b(float v) {
    u64 r; asm("mov.b64 %0, {%1, %1};" : "=l"(r) : "f"(v)); return r;
}
__device__ __forceinline__ u64 pack2f(float lo, float hi) {
    u64 r; asm("mov.b64 %0, {%1, %2};" : "=l"(r) : "f"(lo), "f"(hi)); return r;
}
__device__ __forceinline__ float2 unpack2(u64 v) {
    float2 r; asm("mov.b64 {%0, %1}, %2;" : "=f"(r.x), "=f"(r.y) : "l"(v));
    return r;
}
__device__ __forceinline__ void ffma2(u64& d, u64 a, u64 b) {
    asm("fma.rn.f32x2 %0, %1, %2, %3;" : "=l"(d) : "l"(a), "l"(b), "l"(d));
}
__device__ __forceinline__ u64 add2(u64 a, u64 b) {
    u64 r; asm("add.rn.f32x2 %0, %1, %2;" : "=l"(r) : "l"(a), "l"(b));
    return r;
}
__device__ __forceinline__ float lrelu(float x) {
    return x > 0.f ? x : ALPHA * x;
}

// ---------------- scratch (device globals; no allocation) ----------------
__device__ float g_a1[4 * 256 * 256 * 32];   // after stage 1
__device__ float g_a2[4 * 128 * 128 * 32];   // after stage 2
__device__ float g_a3[4 * 64 * 64 * 32];     // after stage 3
__device__ float g_f0[4 * 64 * 64 * 32];     // after fw0
__device__ float g_f1[4 * 64 * 64 * 32];     // after fw1
__device__ float g_disp[4 * 64 * 64 * 2];    // coarse displacement

// ---------------- stage 1: conv3x3 (Cin=2)+BN+LReLU+pool, subpixel-par ----
__global__ __launch_bounds__(256) void k_conv0(const float* __restrict__ fixed,
                                               const float* __restrict__ moving,
                                               const float* __restrict__ w0) {
    __shared__ float sw[576];                 // (3,3,2,32)
    int t = threadIdx.x;
    for (int i = t; i < 576; i += 256) sw[i] = w0[i];
    __syncthreads();

    int lin = blockIdx.x * 256 + t;           // 4*512*512 threads
    int lane = lin & 31;
    int warp = lin >> 5;
    int dx = lane & 1, dy = (lane >> 4) & 1, xs = (lane >> 1) & 7;
    const int HOUT = 256, WPR = 32;           // pooled-x groups per row
    int b = warp / (WPR * HOUT);
    int rem = warp - b * (WPR * HOUT);
    int py = rem / WPR;
    int px = (rem - py * WPR) * 8 + xs;
    int cy = 2 * py + dy, cx = 2 * px + dx;

    u64 acc[16];
#pragma unroll
    for (int i = 0; i < 16; i++) acc[i] = 0ULL;

#pragma unroll
    for (int ky = 0; ky < 3; ky++) {
        int iy = cy + ky - 1;
        if ((unsigned)iy >= 512u) continue;
#pragma unroll
        for (int kx = 0; kx < 3; kx++) {
            int ix = cx + kx - 1;
            if ((unsigned)ix >= 512u) continue;
            int off = (b << 18) + (iy << 9) + ix;
            u64 v0 = pack2b(fixed[off]);
            u64 v1 = pack2b(moving[off]);
            const ulonglong2* wr =
                reinterpret_cast<const ulonglong2*>(sw + (ky * 3 + kx) * 64);
#pragma unroll
            for (int o = 0; o < 8; o++) {     // ic0: 16 channel-pairs
                ulonglong2 wv = wr[o];
                ffma2(acc[2 * o], v0, wv.x);
                ffma2(acc[2 * o + 1], v0, wv.y);
            }
#pragma unroll
            for (int o = 0; o < 8; o++) {     // ic1
                ulonglong2 wv = wr[8 + o];
                ffma2(acc[2 * o], v1, wv.x);
                ffma2(acc[2 * o + 1], v1, wv.y);
            }
        }
    }

    // BN + LReLU, pool across lanes (dx: ^1, dy: ^16)
    u64 res[16];
#pragma unroll
    for (int p = 0; p < 16; p++) {
        float2 f = unpack2(acc[p]);
        u64 pa = pack2f(lrelu(f.x * BN_SCALE), lrelu(f.y * BN_SCALE));
        pa = add2(pa, __shfl_xor_sync(0xffffffffu, pa, 1));
        pa = add2(pa, __shfl_xor_sync(0xffffffffu, pa, 16));
        float2 r = unpack2(pa);
        res[p] = pack2f(r.x * 0.25f, r.y * 0.25f);
    }
    if (dx == 0 && dy == 0) {
        u64* op = reinterpret_cast<u64*>(
            g_a1 + ((size_t)(b * HOUT + py) * HOUT + px) * 32);
#pragma unroll
        for (int p = 0; p < 16; p++) op[p] = res[p];
    }
}

// ---------------- packed 32->32 conv3x3 tap accumulation ------------------
template <int HIN>
__device__ __forceinline__ void conv32_tap(const float* __restrict__ in,
                                           const float* sw, int b, int cy,
                                           int cx, u64 acc[16]) {
#pragma unroll
    for (int ky = 0; ky < 3; ky++) {
        int iy = cy + ky - 1;
        if ((unsigned)iy >= (unsigned)HIN) continue;
#pragma unroll
        for (int kx = 0; kx < 3; kx++) {
            int ix = cx + kx - 1;
            if ((unsigned)ix >= (unsigned)HIN) continue;
            const float4* ip = reinterpret_cast<const float4*>(
                in + ((size_t)(b * HIN + iy) * HIN + ix) * 32);
            const ulonglong2* wr = reinterpret_cast<const ulonglong2*>(
                sw + (ky * 3 + kx) * 1024);
#pragma unroll
            for (int ic4 = 0; ic4 < 8; ic4++) {
                float4 iv = ip[ic4];
                float vs[4] = {iv.x, iv.y, iv.z, iv.w};
#pragma unroll
                for (int s = 0; s < 4; s++) {
                    u64 vp = pack2b(vs[s]);
                    const ulonglong2* w2 = wr + (ic4 * 4 + s) * 8;
#pragma unroll
                    for (int o = 0; o < 8; o++) {
                        ulonglong2 wv = w2[o];
                        ffma2(acc[2 * o], vp, wv.x);
                        ffma2(acc[2 * o + 1], vp, wv.y);
                    }
                }
            }
        }
    }
}

// ---------------- conv3x3+BN+LReLU+pool (32->32), subpixel-parallel -------
template <int HIN>
__device__ __forceinline__ void convpool_body(const float* __restrict__ in,
                                              float* __restrict__ out,
                                              const float* __restrict__ w) {
    __shared__ float sw[9216];                // (3,3,32,32)
    int t = threadIdx.x;
    for (int i = t; i < 9216; i += 256) sw[i] = w[i];
    __syncthreads();

    const int HOUT = HIN / 2;
    const int WPR = HOUT / 8;
    int lin = blockIdx.x * 256 + t;           // 4*HIN*HIN threads
    int lane = lin & 31;
    int warp = lin >> 5;
    int dx = lane & 1, dy = (lane >> 4) & 1, xs = (lane >> 1) & 7;
    int b = warp / (WPR * HOUT);
    int rem = warp - b * (WPR * HOUT);
    int py = rem / WPR;
    int px = (rem - py * WPR) * 8 + xs;
    int cy = 2 * py + dy, cx = 2 * px + dx;

    u64 acc[16];
#pragma unroll
    for (int i = 0; i < 16; i++) acc[i] = 0ULL;
    conv32_tap<HIN>(in, sw, b, cy, cx, acc);

    u64 res[16];
#pragma unroll
    for (int p = 0; p < 16; p++) {
        float2 f = unpack2(acc[p]);
        u64 pa = pack2f(lrelu(f.x * BN_SCALE), lrelu(f.y * BN_SCALE));
        pa = add2(pa, __shfl_xor_sync(0xffffffffu, pa, 1));
        pa = add2(pa, __shfl_xor_sync(0xffffffffu, pa, 16));
        float2 r = unpack2(pa);
        res[p] = pack2f(r.x * 0.25f, r.y * 0.25f);
    }
    if (dx == 0 && dy == 0) {
        u64* op = reinterpret_cast<u64*>(
            out + ((size_t)(b * HOUT + py) * HOUT + px) * 32);
#pragma unroll
        for (int p = 0; p < 16; p++) op[p] = res[p];
    }
}

__global__ __launch_bounds__(256) void k_stage2(const float* __restrict__ w) {
    convpool_body<256>(g_a1, g_a2, w);
}
__global__ __launch_bounds__(256) void k_stage3(const float* __restrict__ w) {
    convpool_body<128>(g_a2, g_a3, w);
}

// ---------------- conv3x3+BN+LReLU (64x64), oc-split x4 -------------------
__device__ __forceinline__ void fconv_body(const float* __restrict__ in,
                                           float* __restrict__ out,
                                           const float* __restrict__ w) {
    __shared__ float sw[9216];
    int t = threadIdx.x;
    for (int i = t; i < 9216; i += 256) sw[i] = w[i];
    __syncthreads();

    int lin = blockIdx.x * 256 + t;           // 65536 threads
    int lane = lin & 31;
    int warp = lin >> 5;                      // 2048 warps
    int og = warp & 3;                        // oc group (8 channels)
    int pxl = (warp >> 2) * 32 + lane;        // pixel 0..16383
    int b = pxl >> 12;
    int rem = pxl & 4095;
    int y = rem >> 6, x = rem & 63;

    u64 acc[4] = {0ULL, 0ULL, 0ULL, 0ULL};

#pragma unroll
    for (int ky = 0; ky < 3; ky++) {
        int iy = y + ky - 1;
        if ((unsigned)iy >= 64u) continue;
#pragma unroll
        for (int kx = 0; kx < 3; kx++) {
            int ix = x + kx - 1;
            if ((unsigned)ix >= 64u) continue;
            const float4* ip = reinterpret_cast<const float4*>(
                in + ((size_t)((b * 64 + iy) * 64 + ix)) * 32);
            // base at float offset tap*1024 + og*8  (og*2 ulonglong2)
            const ulonglong2* wr = reinterpret_cast<const ulonglong2*>(
                sw + (ky * 3 + kx) * 1024 + og * 8);
#pragma unroll
            for (int ic4 = 0; ic4 < 8; ic4++) {
                float4 iv = ip[ic4];
                float vs[4] = {iv.x, iv.y, iv.z, iv.w};
#pragma unroll
                for (int s = 0; s < 4; s++) {
                    u64 vp = pack2b(vs[s]);
                    // ic stride = 32 floats = 8 ulonglong2 (FIXED: was *4)
                    const ulonglong2* w2 = wr + (ic4 * 4 + s) * 8;
                    ulonglong2 wa = w2[0];
                    ulonglong2 wb = w2[1];
                    ffma2(acc[0], vp, wa.x);
                    ffma2(acc[1], vp, wa.y);
                    ffma2(acc[2], vp, wb.x);
                    ffma2(acc[3], vp, wb.y);
                }
            }
        }
    }

    float* op = out + (size_t)pxl * 32 + og * 8;
    float4 r0, r1;
    float2 f0 = unpack2(acc[0]), f1 = unpack2(acc[1]);
    float2 f2 = unpack2(acc[2]), f3 = unpack2(acc[3]);
    r0.x = lrelu(f0.x * BN_SCALE); r0.y = lrelu(f0.y * BN_SCALE);
    r0.z = lrelu(f1.x * BN_SCALE); r0.w = lrelu(f1.y * BN_SCALE);
    r1.x = lrelu(f2.x * BN_SCALE); r1.y = lrelu(f2.y * BN_SCALE);
    r1.z = lrelu(f3.x * BN_SCALE); r1.w = lrelu(f3.y * BN_SCALE);
    reinterpret_cast<float4*>(op)[0] = r0;
    reinterpret_cast<float4*>(op)[1] = r1;
}

__global__ __launch_bounds__(256) void k_fconv0(const float* __restrict__ w) {
    fconv_body(g_a3, g_f0, w);
}
__global__ __launch_bounds__(256) void k_fconv1(const float* __restrict__ w) {
    fconv_body(g_f0, g_f1, w);
}

// ---------------- pointwise pw0 (LReLU) then pw1 -> disp ------------------
__global__ __launch_bounds__(128) void k_pw(const float* __restrict__ pw0,
                                            const float* __restrict__ pw1) {
    __shared__ float s0[1024];                // (1,1,32,32)
    __shared__ float s1[64];                  // (1,1,32,2)
    int t = threadIdx.x;
    for (int i = t; i < 1024; i += 128) s0[i] = pw0[i];
    if (t < 64) s1[t] = pw1[t];
    __syncthreads();

    int idx = blockIdx.x * 128 + t;           // 16384
    const float4* ip = reinterpret_cast<const float4*>(g_f1 + (size_t)idx * 32);
    float xv[32];
#pragma unroll
    for (int i = 0; i < 8; i++) {
        float4 v = ip[i];
        xv[i * 4 + 0] = v.x; xv[i * 4 + 1] = v.y;
        xv[i * 4 + 2] = v.z; xv[i * 4 + 3] = v.w;
    }
    float d0 = 0.f, d1 = 0.f;
#pragma unroll
    for (int oc = 0; oc < 32; oc++) {
        float a = 0.f;
#pragma unroll
        for (int ic = 0; ic < 32; ic++) a += xv[ic] * s0[ic * 32 + oc];
        a = lrelu(a);
        d0 += a * s1[oc * 2 + 0];
        d1 += a * s1[oc * 2 + 1];
    }
    g_disp[idx * 2 + 0] = d0;
    g_disp[idx * 2 + 1] = d1;
}

// ---------------- B-spline upsample + bilinear warp + outputs -------------
__global__ __launch_bounds__(256) void k_warp(const float* __restrict__ moving,
                                              float* __restrict__ out) {
    int idx = blockIdx.x * 256 + threadIdx.x; // 4*512*512
    int b = idx >> 18;
    int rem = idx & 262143;
    int h = rem >> 9, w = rem & 511;

    float xv = fminf(w * 0.125f, 63.f);
    float yv = fminf(h * 0.125f, 63.f);
    int ii = (int)xv;
    int jj = (int)yv;
    float u = xv * 0.015625f;                 // /64
    float v = yv * 0.015625f;

    float u2 = u * u, u3 = u2 * u;
    float v2 = v * v, v3 = v2 * v;
    float Bu[4] = { -u3 + 3.f * u2 - 3.f * u + 1.f,
                     3.f * u3 - 6.f * u2 + 4.f,
                    -3.f * u3 + 3.f * u2 + 3.f * u + 1.f,
                     u3 };
    float Bv[4] = { -v3 + 3.f * v2 - 3.f * v + 1.f,
                     3.f * v3 - 6.f * v2 + 4.f,
                    -3.f * v3 + 3.f * v2 + 3.f * v + 1.f,
                     v3 };

    const float2* dp = reinterpret_cast<const float2*>(g_disp);
    float i0 = 0.f, i1 = 0.f;
#pragma unroll
    for (int m = 0; m < 4; m++) {
        int ry = jj + m - 1;
        if ((unsigned)ry >= 64u) continue;
        float s0 = 0.f, s1 = 0.f;
#pragma unroll
        for (int n = 0; n < 4; n++) {
            int rx = ii + n - 1;
            if ((unsigned)rx >= 64u) continue;
            float2 d = dp[(b * 64 + ry) * 64 + rx];
            s0 += Bv[n] * d.x;
            s1 += Bv[n] * d.y;
        }
        i0 += Bu[m] * s0;
        i1 += Bu[m] * s1;
    }

    float wxf = i0 + (float)w;
    float wyf = i1 + (float)h;

    float fx = floorf(wxf);
    float x0 = fminf(fmaxf(fx, 0.f), 511.f);
    float x1 = fminf(fmaxf(fx + 1.f, 0.f), 511.f);
    float fy = floorf(wyf);
    float y0 = fminf(fmaxf(fy, 0.f), 511.f);
    float y1 = fminf(fmaxf(fy + 1.f, 0.f), 511.f);
    int x0i = (int)x0, x1i = (int)x1, y0i = (int)y0, y1i = (int)y1;

    const float* im = moving + ((size_t)b << 18);
    float Q1 = im[y0i * 512 + x0i];
    float Q2 = im[y1i * 512 + x0i];
    float Q3 = im[y0i * 512 + x1i];
    float Q4 = im[y1i * 512 + x1i];

    float invx = 1.f / (x1 - x0 + 1e-5f);
    float wxr = (x1 - wxf) * invx;
    float wxl = (wxf - x0) * invx;
    float R1 = wxr * Q1 + wxl * Q3;
    float R2 = wxr * Q2 + wxl * Q4;
    float invy = 1.f / (y1 - y0 + 1e-5f);
    float res = (y1 - wyf) * invy * R1 + (wyf - y0) * invy * R2;

    out[(b << 18) + (h << 9) + w] = res;
    const int WOFF = 4 * 512 * 512;
    out[WOFF + ((b * 2 + 0) << 18) + (h << 9) + w] = wxf;
    out[WOFF + ((b * 2 + 1) << 18) + (h << 9) + w] = wyf;
}

// ---------------- launch ---------------------------------------------------
extern "C" void kernel_launch(void* const* d_in, const int* in_sizes, int n_in,
                              void* d_out, int out_size) {
    const float* fixed  = (const float*)d_in[0];
    const float* moving = (const float*)d_in[1];
    const float* w0  = (const float*)d_in[2];
    const float* w1  = (const float*)d_in[3];
    const float* w2  = (const float*)d_in[4];
    const float* fw0 = (const float*)d_in[5];
    const float* fw1 = (const float*)d_in[6];
    const float* pw0 = (const float*)d_in[7];
    const float* pw1 = (const float*)d_in[8];
    float* out = (float*)d_out;

    k_conv0<<<4096, 256>>>(fixed, moving, w0);   // 512 -> 256 (subpix-par)
    k_stage2<<<1024, 256>>>(w1);                 // 256 -> 128 (subpix-par)
    k_stage3<<<256, 256>>>(w2);                  // 128 -> 64  (subpix-par)
    k_fconv0<<<256, 256>>>(fw0);                 // 64x64 conv (oc-split x4)
    k_fconv1<<<256, 256>>>(fw1);                 // 64x64 conv (oc-split x4)
    k_pw<<<128, 128>>>(pw0, pw1);                // pointwise -> disp
    k_warp<<<4096, 256>>>(moving, out);          // upsample + warp
}

// round 10
// speedup vs baseline: 2.4689x; 1.8875x over previous
#include <cuda_runtime.h>
#include <math.h>

#define ALPHA 0.2f
#define BN_SCALE 0.99950037f   // 1/sqrt(1 + 1e-3)

typedef unsigned long long u64;

// ---------------- packed f32x2 helpers ------------------------------------
__device__ __forceinline__ u64 pack2b(float v) {
    u64 r; asm("mov.b64 %0, {%1, %1};" : "=l"(r) : "f"(v)); return r;
}
__device__ __forceinline__ u64 pack2f(float lo, float hi) {
    u64 r; asm("mov.b64 %0, {%1, %2};" : "=l"(r) : "f"(lo), "f"(hi)); return r;
}
__device__ __forceinline__ float2 unpack2(u64 v) {
    float2 r; asm("mov.b64 {%0, %1}, %2;" : "=f"(r.x), "=f"(r.y) : "l"(v));
    return r;
}
__device__ __forceinline__ void ffma2(u64& d, u64 a, u64 b) {
    asm("fma.rn.f32x2 %0, %1, %2, %0;" : "+l"(d) : "l"(a), "l"(b));
}
__device__ __forceinline__ float lrelu(float x) {
    return x > 0.f ? x : ALPHA * x;
}
__device__ __forceinline__ float f4c(const float4& v, int s) {
    return s == 0 ? v.x : s == 1 ? v.y : s == 2 ? v.z : v.w;
}

// ---------------- scratch (device globals; no allocation) ----------------
__device__ float g_a1[4 * 256 * 256 * 32];
__device__ float g_a2[4 * 128 * 128 * 32];
__device__ float g_a3[4 * 64 * 64 * 32];
__device__ float g_f0[4 * 64 * 64 * 32];
__device__ float g_f1[4 * 64 * 64 * 32];
__device__ float g_disp[4 * 64 * 64 * 2];

// ============ stage 1: conv3x3 Cin=2 + BN + LReLU + pool, 8px/thread ======
// thread = (b, py, cell-pair pp of 128, og of 4); 4x2 pre-pool pixels, 8 oc.
__global__ __launch_bounds__(128) void k_conv0(const float* __restrict__ fixed,
                                               const float* __restrict__ moving,
                                               const float* __restrict__ w0) {
    __shared__ float sw[576];                 // (3,3,2,32)
    int t = threadIdx.x;
    for (int i = t; i < 576; i += 128) sw[i] = w0[i];
    __syncthreads();

    int lin = blockIdx.x * 128 + t;           // 4*256*128*4 = 524288
    int og = lin & 3;
    int idx = lin >> 2;
    int pp = idx & 127;                       // 128 cell-pairs per row (FIX)
    int py = (idx >> 7) & 255;
    int b = idx >> 15;
    int cx0 = 4 * pp, cy0 = 2 * py;

    u64 acc[8][4];
#pragma unroll
    for (int i = 0; i < 8; i++)
#pragma unroll
        for (int p = 0; p < 4; p++) acc[i][p] = 0ULL;

#pragma unroll
    for (int iy = 0; iy < 4; iy++) {
        int gy = cy0 - 1 + iy;
        bool rowok = (unsigned)gy < 512u;
        u64 pf[6], pm[6];
#pragma unroll
        for (int c = 0; c < 6; c++) {
            int gx = cx0 - 1 + c;
            bool ok = rowok && (unsigned)gx < 512u;
            int off = (b << 18) + (gy << 9) + gx;
            pf[c] = ok ? pack2b(fixed[off]) : 0ULL;
            pm[c] = ok ? pack2b(moving[off]) : 0ULL;
        }
#pragma unroll
        for (int r = 0; r < 2; r++) {
            int ky = iy - r;
            if (ky < 0 || ky > 2) continue;
#pragma unroll
            for (int kx = 0; kx < 3; kx++) {
                const ulonglong2* wf = reinterpret_cast<const ulonglong2*>(
                    sw + (ky * 3 + kx) * 64 + og * 8);
                const ulonglong2* wm = reinterpret_cast<const ulonglong2*>(
                    sw + (ky * 3 + kx) * 64 + 32 + og * 8);
                ulonglong2 wfa = wf[0], wfb = wf[1];
                ulonglong2 wma = wm[0], wmb = wm[1];
#pragma unroll
                for (int c = 0; c < 4; c++) {
                    u64 vf = pf[c + kx], vm = pm[c + kx];
                    ffma2(acc[r * 4 + c][0], vf, wfa.x);
                    ffma2(acc[r * 4 + c][1], vf, wfa.y);
                    ffma2(acc[r * 4 + c][2], vf, wfb.x);
                    ffma2(acc[r * 4 + c][3], vf, wfb.y);
                    ffma2(acc[r * 4 + c][0], vm, wma.x);
                    ffma2(acc[r * 4 + c][1], vm, wma.y);
                    ffma2(acc[r * 4 + c][2], vm, wmb.x);
                    ffma2(acc[r * 4 + c][3], vm, wmb.y);
                }
            }
        }
    }

#pragma unroll
    for (int cc = 0; cc < 2; cc++) {
        u64 resv[4];
#pragma unroll
        for (int p = 0; p < 4; p++) {
            float2 f00 = unpack2(acc[2 * cc][p]);
            float2 f01 = unpack2(acc[2 * cc + 1][p]);
            float2 f10 = unpack2(acc[4 + 2 * cc][p]);
            float2 f11 = unpack2(acc[4 + 2 * cc + 1][p]);
            float lo = lrelu(f00.x * BN_SCALE) + lrelu(f01.x * BN_SCALE) +
                       lrelu(f10.x * BN_SCALE) + lrelu(f11.x * BN_SCALE);
            float hi = lrelu(f00.y * BN_SCALE) + lrelu(f01.y * BN_SCALE) +
                       lrelu(f10.y * BN_SCALE) + lrelu(f11.y * BN_SCALE);
            resv[p] = pack2f(lo * 0.25f, hi * 0.25f);
        }
        int px = 2 * pp + cc;
        ulonglong2* op = reinterpret_cast<ulonglong2*>(
            g_a1 + ((size_t)(b * 256 + py) * 256 + px) * 32 + og * 8);
        op[0] = make_ulonglong2(resv[0], resv[1]);
        op[1] = make_ulonglong2(resv[2], resv[3]);
    }
}

// ============ conv3x3 32->32 + BN + LReLU + pool, 8px/thread ==============
template <int HIN>
__device__ __forceinline__ void convpool_body(const float* __restrict__ in,
                                              float* __restrict__ out,
                                              const float* __restrict__ w) {
    __shared__ float sw[9216];                // (3,3,32,32)
    int t = threadIdx.x;
    for (int i = t; i < 9216; i += 128) sw[i] = w[i];
    __syncthreads();

    const int HOUT = HIN / 2;
    const int PPW = HOUT / 2;
    int lin = blockIdx.x * 128 + t;           // 4*HOUT*PPW*4 threads
    int og = lin & 3;
    int idx = lin >> 2;
    int pp = idx % PPW;
    int tmp = idx / PPW;
    int py = tmp % HOUT;
    int b = tmp / HOUT;
    int cx0 = 4 * pp, cy0 = 2 * py;

    u64 acc[8][4];
#pragma unroll
    for (int i = 0; i < 8; i++)
#pragma unroll
        for (int p = 0; p < 4; p++) acc[i][p] = 0ULL;

    for (int ic4 = 0; ic4 < 8; ic4++) {
#pragma unroll
        for (int iy = 0; iy < 4; iy++) {
            int gy = cy0 - 1 + iy;
            bool rowok = (unsigned)gy < (unsigned)HIN;
            float4 rowv[6];
#pragma unroll
            for (int c = 0; c < 6; c++) {
                int gx = cx0 - 1 + c;
                if (rowok && (unsigned)gx < (unsigned)HIN)
                    rowv[c] = reinterpret_cast<const float4*>(
                        in + ((size_t)(b * HIN + gy) * HIN + gx) * 32)[ic4];
                else
                    rowv[c] = make_float4(0.f, 0.f, 0.f, 0.f);
            }
#pragma unroll
            for (int s = 0; s < 4; s++) {
                u64 pu[6];
#pragma unroll
                for (int c = 0; c < 6; c++) pu[c] = pack2b(f4c(rowv[c], s));
#pragma unroll
                for (int r = 0; r < 2; r++) {
                    int ky = iy - r;
                    if (ky < 0 || ky > 2) continue;
#pragma unroll
                    for (int kx = 0; kx < 3; kx++) {
                        const ulonglong2* wp =
                            reinterpret_cast<const ulonglong2*>(
                                sw + (ky * 3 + kx) * 1024 + (ic4 * 4 + s) * 32 +
                                og * 8);
                        ulonglong2 wa = wp[0], wb = wp[1];
#pragma unroll
                        for (int c = 0; c < 4; c++) {
                            u64 v = pu[c + kx];
                            ffma2(acc[r * 4 + c][0], v, wa.x);
                            ffma2(acc[r * 4 + c][1], v, wa.y);
                            ffma2(acc[r * 4 + c][2], v, wb.x);
                            ffma2(acc[r * 4 + c][3], v, wb.y);
                        }
                    }
                }
            }
        }
    }

#pragma unroll
    for (int cc = 0; cc < 2; cc++) {
        u64 resv[4];
#pragma unroll
        for (int p = 0; p < 4; p++) {
            float2 f00 = unpack2(acc[2 * cc][p]);
            float2 f01 = unpack2(acc[2 * cc + 1][p]);
            float2 f10 = unpack2(acc[4 + 2 * cc][p]);
            float2 f11 = unpack2(acc[4 + 2 * cc + 1][p]);
            float lo = lrelu(f00.x * BN_SCALE) + lrelu(f01.x * BN_SCALE) +
                       lrelu(f10.x * BN_SCALE) + lrelu(f11.x * BN_SCALE);
            float hi = lrelu(f00.y * BN_SCALE) + lrelu(f01.y * BN_SCALE) +
                       lrelu(f10.y * BN_SCALE) + lrelu(f11.y * BN_SCALE);
            resv[p] = pack2f(lo * 0.25f, hi * 0.25f);
        }
        int px = 2 * pp + cc;
        ulonglong2* op = reinterpret_cast<ulonglong2*>(
            out + ((size_t)(b * HOUT + py) * HOUT + px) * 32 + og * 8);
        op[0] = make_ulonglong2(resv[0], resv[1]);
        op[1] = make_ulonglong2(resv[2], resv[3]);
    }
}

__global__ __launch_bounds__(128) void k_stage2(const float* __restrict__ w) {
    convpool_body<256>(g_a1, g_a2, w);
}
__global__ __launch_bounds__(128) void k_stage3(const float* __restrict__ w) {
    convpool_body<128>(g_a2, g_a3, w);
}

// ============ conv3x3 32->32 + BN + LReLU (64x64), 4px x 4oc /thread ======
__device__ __forceinline__ void fconv_body(const float* __restrict__ in,
                                           float* __restrict__ out,
                                           const float* __restrict__ w) {
    __shared__ float sw[9216];
    int t = threadIdx.x;
    for (int i = t; i < 9216; i += 128) sw[i] = w[i];
    __syncthreads();

    int lin = blockIdx.x * 128 + t;           // 4*64*16*8 = 32768
    int og = lin & 7;                         // 4 oc each
    int idx = lin >> 3;
    int xb = idx & 15;
    int y = (idx >> 4) & 63;
    int b = idx >> 10;
    int x0 = 4 * xb;

    u64 acc[4][2];
#pragma unroll
    for (int c = 0; c < 4; c++) { acc[c][0] = 0ULL; acc[c][1] = 0ULL; }

    for (int ic4 = 0; ic4 < 8; ic4++) {
#pragma unroll
        for (int ky = 0; ky < 3; ky++) {
            int gy = y + ky - 1;
            bool rowok = (unsigned)gy < 64u;
            float4 rowv[6];
#pragma unroll
            for (int c = 0; c < 6; c++) {
                int gx = x0 - 1 + c;
                if (rowok && (unsigned)gx < 64u)
                    rowv[c] = reinterpret_cast<const float4*>(
                        in + ((size_t)((b * 64 + gy) * 64 + gx)) * 32)[ic4];
                else
                    rowv[c] = make_float4(0.f, 0.f, 0.f, 0.f);
            }
#pragma unroll
            for (int s = 0; s < 4; s++) {
                u64 pu[6];
#pragma unroll
                for (int c = 0; c < 6; c++) pu[c] = pack2b(f4c(rowv[c], s));
#pragma unroll
                for (int kx = 0; kx < 3; kx++) {
                    const ulonglong2* wp = reinterpret_cast<const ulonglong2*>(
                        sw + (ky * 3 + kx) * 1024 + (ic4 * 4 + s) * 32 + og * 4);
                    ulonglong2 wv = wp[0];
#pragma unroll
                    for (int c = 0; c < 4; c++) {
                        u64 v = pu[c + kx];
                        ffma2(acc[c][0], v, wv.x);
                        ffma2(acc[c][1], v, wv.y);
                    }
                }
            }
        }
    }

#pragma unroll
    for (int c = 0; c < 4; c++) {
        float2 f0 = unpack2(acc[c][0]);
        float2 f1 = unpack2(acc[c][1]);
        float4 r;
        r.x = lrelu(f0.x * BN_SCALE);
        r.y = lrelu(f0.y * BN_SCALE);
        r.z = lrelu(f1.x * BN_SCALE);
        r.w = lrelu(f1.y * BN_SCALE);
        int pxl = (b * 64 + y) * 64 + x0 + c;
        reinterpret_cast<float4*>(out + (size_t)pxl * 32 + og * 4)[0] = r;
    }
}

__global__ __launch_bounds__(128) void k_fconv0(const float* __restrict__ w) {
    fconv_body(g_a3, g_f0, w);
}
__global__ __launch_bounds__(128) void k_fconv1(const float* __restrict__ w) {
    fconv_body(g_f0, g_f1, w);
}

// ---------------- pointwise pw0 (LReLU) then pw1 -> disp ------------------
__global__ __launch_bounds__(128) void k_pw(const float* __restrict__ pw0,
                                            const float* __restrict__ pw1) {
    __shared__ float s0[1024];
    __shared__ float s1[64];
    int t = threadIdx.x;
    for (int i = t; i < 1024; i += 128) s0[i] = pw0[i];
    if (t < 64) s1[t] = pw1[t];
    __syncthreads();

    int idx = blockIdx.x * 128 + t;           // 16384
    const float4* ip = reinterpret_cast<const float4*>(g_f1 + (size_t)idx * 32);
    float xv[32];
#pragma unroll
    for (int i = 0; i < 8; i++) {
        float4 v = ip[i];
        xv[i * 4 + 0] = v.x; xv[i * 4 + 1] = v.y;
        xv[i * 4 + 2] = v.z; xv[i * 4 + 3] = v.w;
    }
    float d0 = 0.f, d1 = 0.f;
#pragma unroll
    for (int oc = 0; oc < 32; oc++) {
        float a = 0.f;
#pragma unroll
        for (int ic = 0; ic < 32; ic++) a += xv[ic] * s0[ic * 32 + oc];
        a = lrelu(a);
        d0 += a * s1[oc * 2 + 0];
        d1 += a * s1[oc * 2 + 1];
    }
    g_disp[idx * 2 + 0] = d0;
    g_disp[idx * 2 + 1] = d1;
}

// ---------------- B-spline upsample + bilinear warp + outputs -------------
__global__ __launch_bounds__(256) void k_warp(const float* __restrict__ moving,
                                              float* __restrict__ out) {
    int idx = blockIdx.x * 256 + threadIdx.x; // 4*512*512
    int b = idx >> 18;
    int rem = idx & 262143;
    int h = rem >> 9, w = rem & 511;

    float xv = fminf(w * 0.125f, 63.f);
    float yv = fminf(h * 0.125f, 63.f);
    int ii = (int)xv;
    int jj = (int)yv;
    float u = xv * 0.015625f;
    float v = yv * 0.015625f;

    float u2 = u * u, u3 = u2 * u;
    float v2 = v * v, v3 = v2 * v;
    float Bu[4] = { -u3 + 3.f * u2 - 3.f * u + 1.f,
                     3.f * u3 - 6.f * u2 + 4.f,
                    -3.f * u3 + 3.f * u2 + 3.f * u + 1.f,
                     u3 };
    float Bv[4] = { -v3 + 3.f * v2 - 3.f * v + 1.f,
                     3.f * v3 - 6.f * v2 + 4.f,
                    -3.f * v3 + 3.f * v2 + 3.f * v + 1.f,
                     v3 };

    const float2* dp = reinterpret_cast<const float2*>(g_disp);
    float i0 = 0.f, i1 = 0.f;
#pragma unroll
    for (int m = 0; m < 4; m++) {
        int ry = jj + m - 1;
        if ((unsigned)ry >= 64u) continue;
        float s0 = 0.f, s1 = 0.f;
#pragma unroll
        for (int n = 0; n < 4; n++) {
            int rx = ii + n - 1;
            if ((unsigned)rx >= 64u) continue;
            float2 d = dp[(b * 64 + ry) * 64 + rx];
            s0 += Bv[n] * d.x;
            s1 += Bv[n] * d.y;
        }
        i0 += Bu[m] * s0;
        i1 += Bu[m] * s1;
    }

    float wxf = i0 + (float)w;
    float wyf = i1 + (float)h;

    float fx = floorf(wxf);
    float x0 = fminf(fmaxf(fx, 0.f), 511.f);
    float x1 = fminf(fmaxf(fx + 1.f, 0.f), 511.f);
    float fy = floorf(wyf);
    float y0 = fminf(fmaxf(fy, 0.f), 511.f);
    float y1 = fminf(fmaxf(fy + 1.f, 0.f), 511.f);
    int x0i = (int)x0, x1i = (int)x1, y0i = (int)y0, y1i = (int)y1;

    const float* im = moving + ((size_t)b << 18);
    float Q1 = im[y0i * 512 + x0i];
    float Q2 = im[y1i * 512 + x0i];
    float Q3 = im[y0i * 512 + x1i];
    float Q4 = im[y1i * 512 + x1i];

    float invx = 1.f / (x1 - x0 + 1e-5f);
    float wxr = (x1 - wxf) * invx;
    float wxl = (wxf - x0) * invx;
    float R1 = wxr * Q1 + wxl * Q3;
    float R2 = wxr * Q2 + wxl * Q4;
    float invy = 1.f / (y1 - y0 + 1e-5f);
    float res = (y1 - wyf) * invy * R1 + (wyf - y0) * invy * R2;

    out[(b << 18) + (h << 9) + w] = res;
    const int WOFF = 4 * 512 * 512;
    out[WOFF + ((b * 2 + 0) << 18) + (h << 9) + w] = wxf;
    out[WOFF + ((b * 2 + 1) << 18) + (h << 9) + w] = wyf;
}

// ---------------- launch ---------------------------------------------------
extern "C" void kernel_launch(void* const* d_in, const int* in_sizes, int n_in,
                              void* d_out, int out_size) {
    const float* fixed  = (const float*)d_in[0];
    const float* moving = (const float*)d_in[1];
    const float* w0  = (const float*)d_in[2];
    const float* w1  = (const float*)d_in[3];
    const float* w2  = (const float*)d_in[4];
    const float* fw0 = (const float*)d_in[5];
    const float* fw1 = (const float*)d_in[6];
    const float* pw0 = (const float*)d_in[7];
    const float* pw1 = (const float*)d_in[8];
    float* out = (float*)d_out;

    k_conv0<<<4096, 128>>>(fixed, moving, w0);   // 512 -> 256, 8px/thread (FIX: full width)
    k_stage2<<<1024, 128>>>(w1);                 // 256 -> 128, 8px/thread
    k_stage3<<<256, 128>>>(w2);                  // 128 -> 64,  8px/thread
    k_fconv0<<<256, 128>>>(fw0);                 // 64x64, 4px x 4oc
    k_fconv1<<<256, 128>>>(fw1);                 // 64x64, 4px x 4oc
    k_pw<<<128, 128>>>(pw0, pw1);                // pointwise -> disp
    k_warp<<<4096, 256>>>(moving, out);          // upsample + warp
}